// round 4
// baseline (speedup 1.0000x reference)
#include <cuda_runtime.h>

// Problem constants (fixed by the dataset)
#define Bn 16
#define Cn 128
#define Hn 64
#define Wn 64
#define Kn 16
#define NPIECE 15

// ---------------------------------------------------------------------------
// Compile-time: per-piece 4x4 matrices mapping (al0..al3) -> Newton coeffs
// in UNIT local coordinate u in [0,1] (nodes 0, 1/3, 2/3, 1).
// All arithmetic in constexpr double; zero runtime divisions.
// ---------------------------------------------------------------------------
constexpr double kn_c(int i) {
    return i <= 3 ? -1.0 : (i >= 16 ? 1.0 : -1.0 + (double)(i - 3) * (2.0 / 13.0));
}

struct B4 { double n[4]; };

constexpr B4 basis_at(double tt, int sr) {
    const int span = sr + 3;
    double lft[4] = {0, 0, 0, 0}, rgt[4] = {0, 0, 0, 0}, Nb[4] = {1.0, 0, 0, 0};
    for (int j = 1; j <= 3; j++) {
        lft[j] = tt - kn_c(span + 1 - j);
        rgt[j] = kn_c(span + j) - tt;
        double saved = 0.0;
        for (int r = 0; r < j; r++) {
            double den = rgt[r + 1] + lft[j - r];
            double tmp = Nb[r] / den;
            Nb[r] = saved + rgt[r + 1] * tmp;
            saved = lft[j - r] * tmp;
        }
        Nb[j] = saved;
    }
    B4 b = {{Nb[0], Nb[1], Nb[2], Nb[3]}};
    return b;
}

struct Tab { float t[13][4][4]; };   // [piece][newton coeff][alpha j]

constexpr Tab make_tab() {
    Tab T = {};
    const double h = 2.0 / 13.0;
    for (int sr = 0; sr < 13; sr++) {
        double t0 = -1.0 + (double)sr * h;
        double w[4][4] = {};
        for (int n = 0; n < 4; n++) {
            B4 b = basis_at(t0 + (double)n * (h / 3.0), sr);
            for (int j = 0; j < 4; j++) w[n][j] = b.n[j];
        }
        // Newton divided differences on unit nodes 0, 1/3, 2/3, 1
        for (int j = 0; j < 4; j++) {
            T.t[sr][0][j] = (float)(w[0][j]);
            T.t[sr][1][j] = (float)((w[1][j] - w[0][j]) * 3.0);
            T.t[sr][2][j] = (float)((w[2][j] - 2.0 * w[1][j] + w[0][j]) * 4.5);
            T.t[sr][3][j] = (float)((w[3][j] - 3.0 * w[2][j] + 3.0 * w[1][j] - w[0][j]) * 4.5);
        }
    }
    return T;
}

__constant__ Tab c_tab = make_tab();

// ---------------------------------------------------------------------------
// Per-element evaluation: ~18 SASS ops, 2 conflict-free LDS.64.
//   t  = x*a + b            (no clip needed: spline==0 outside [-1,1])
//   uf = t*6.5 + 7.5        (piece index + 1, in float)
//   k  = clamp(trunc(uf), 0, 13);  k=14 iff t > 1 (strict; t==1 -> piece 12)
//   u  = uf - (float)k      (unit local coordinate; garbage for sentinels, ok)
// ---------------------------------------------------------------------------
__device__ __forceinline__ float eval_one(float x, float av, float bv, float gv,
                                          const float2* d01, const float2* d23) {
    float t  = fmaf(x, av, bv);
    float uf = fmaf(t, 6.5f, 7.5f);
    int k0 = (int)uf;                       // trunc == floor for uf >= 0
    int k  = min(max(k0, 0), 13);
    float srf = (float)k;
    float u = uf - srf;
    if (t > 1.0f) k = 14;                   // strict: t==1 stays in piece 12
    float2 ab = d01[k];                     // {d0, d1}
    float2 cd = d23[k];                     // {d2, d3}
    float p = fmaf(cd.y, u - (2.0f / 3.0f), cd.x);
    p = fmaf(p, u - (1.0f / 3.0f), ab.y);
    p = fmaf(p, u, ab.x);                   // d0 includes bias
    return fmaf(gv, x, p);
}

// ---------------------------------------------------------------------------
// grid = 4096 blocks (2 per (b,c) plane), block = 256, 2 float4 per thread.
// ---------------------------------------------------------------------------
__global__ void __launch_bounds__(256)
kan_spline_fused(const float4* __restrict__ x,
                 const float*  __restrict__ a,
                 const float*  __restrict__ b,
                 const float*  __restrict__ alpha,
                 const float*  __restrict__ gain,
                 const float*  __restrict__ bias,
                 float4* __restrict__ out) {
    // float2 SoA: entry k at banks {2k, 2k+1} -> conflict-free LDS.64
    __shared__ float2 d01[16];
    __shared__ float2 d23[16];

    int bid = blockIdx.x;
    int c = (bid >> 1) & (Cn - 1);
    int tid = threadIdx.x;

    if (tid < NPIECE) {
        float bv = bias[c];
        float d0 = bv, d1 = 0.0f, d2 = 0.0f, d3 = 0.0f;
        int sr = tid - 1;                    // -1..13 ; valid pieces 0..12
        if (sr >= 0 && sr <= 12) {
            float al0 = alpha[c * Kn + sr];
            float al1 = alpha[c * Kn + sr + 1];
            float al2 = alpha[c * Kn + sr + 2];
            float al3 = alpha[c * Kn + sr + 3];
            const float (*T)[4] = c_tab.t[sr];
            d0 = fmaf(T[0][0], al0, fmaf(T[0][1], al1, fmaf(T[0][2], al2, fmaf(T[0][3], al3, bv))));
            d1 = fmaf(T[1][0], al0, fmaf(T[1][1], al1, fmaf(T[1][2], al2, T[1][3] * al3)));
            d2 = fmaf(T[2][0], al0, fmaf(T[2][1], al1, fmaf(T[2][2], al2, T[2][3] * al3)));
            d3 = fmaf(T[3][0], al0, fmaf(T[3][1], al1, fmaf(T[3][2], al2, T[3][3] * al3)));
        }
        d01[tid] = make_float2(d0, d1);
        d23[tid] = make_float2(d2, d3);
    }
    float av = __ldg(a + c);
    float bv2 = __ldg(b + c);
    float gv = __ldg(gain + c);
    __syncthreads();

    int base = bid * 512 + tid;
    float4 x0 = __ldg(x + base);
    float4 x1 = __ldg(x + base + 256);

    float4 o0, o1;
    o0.x = eval_one(x0.x, av, bv2, gv, d01, d23);
    o0.y = eval_one(x0.y, av, bv2, gv, d01, d23);
    o0.z = eval_one(x0.z, av, bv2, gv, d01, d23);
    o0.w = eval_one(x0.w, av, bv2, gv, d01, d23);
    o1.x = eval_one(x1.x, av, bv2, gv, d01, d23);
    o1.y = eval_one(x1.y, av, bv2, gv, d01, d23);
    o1.z = eval_one(x1.z, av, bv2, gv, d01, d23);
    o1.w = eval_one(x1.w, av, bv2, gv, d01, d23);

    out[base]       = o0;
    out[base + 256] = o1;
}

// ---------------------------------------------------------------------------
// Launch: d_in order = x, a, b, alpha, id_gain, bias
// ---------------------------------------------------------------------------
extern "C" void kernel_launch(void* const* d_in, const int* in_sizes, int n_in,
                              void* d_out, int out_size) {
    const float* x      = (const float*)d_in[0];
    const float* a      = (const float*)d_in[1];
    const float* b      = (const float*)d_in[2];
    const float* alpha  = (const float*)d_in[3];
    const float* gain   = (const float*)d_in[4];
    const float* bias   = (const float*)d_in[5];
    float* out = (float*)d_out;

    const int total4 = (Bn * Cn * Hn * Wn) / 4;   // 2,097,152 float4
    const int blocks = total4 / 512;              // 4096
    kan_spline_fused<<<blocks, 256>>>((const float4*)x, a, b, alpha, gain, bias,
                                      (float4*)out);
}

// round 5
// speedup vs baseline: 1.6318x; 1.6318x over previous
#include <cuda_runtime.h>

// Problem constants (fixed by the dataset)
#define Bn 16
#define Cn 128
#define Hn 64
#define Wn 64
#define Kn 16

// ---------------------------------------------------------------------------
// Compile-time: per-piece 4x4 matrices M[sr][m][j] = monomial coeff m (of u in
// [0,1]) of basis function alpha_{sr+j}'s polynomial on piece sr.
// All arithmetic in constexpr double; zero runtime divisions for the spline.
// ---------------------------------------------------------------------------
constexpr double kn_c(int i) {
    return i <= 3 ? -1.0 : (i >= 16 ? 1.0 : -1.0 + (double)(i - 3) * (2.0 / 13.0));
}

struct B4 { double n[4]; };

constexpr B4 basis_at(double tt, int sr) {
    const int span = sr + 3;
    double lft[4] = {0, 0, 0, 0}, rgt[4] = {0, 0, 0, 0}, Nb[4] = {1.0, 0, 0, 0};
    for (int j = 1; j <= 3; j++) {
        lft[j] = tt - kn_c(span + 1 - j);
        rgt[j] = kn_c(span + j) - tt;
        double saved = 0.0;
        for (int r = 0; r < j; r++) {
            double den = rgt[r + 1] + lft[j - r];
            double tmp = Nb[r] / den;
            Nb[r] = saved + rgt[r + 1] * tmp;
            saved = lft[j - r] * tmp;
        }
        Nb[j] = saved;
    }
    B4 b = {{Nb[0], Nb[1], Nb[2], Nb[3]}};
    return b;
}

struct Tab { float m[13][4][4]; };   // [piece][monomial power][alpha j]

constexpr Tab make_tab() {
    Tab T = {};
    const double h = 2.0 / 13.0;
    for (int sr = 0; sr < 13; sr++) {
        double t0 = -1.0 + (double)sr * h;
        for (int j = 0; j < 4; j++) {
            double y0 = basis_at(t0, sr).n[j];
            double y1 = basis_at(t0 + h / 3.0, sr).n[j];
            double y2 = basis_at(t0 + 2.0 * h / 3.0, sr).n[j];
            double y3 = basis_at(t0 + h, sr).n[j];
            // Newton divided differences on unit nodes 0,1/3,2/3,1
            double d0 = y0;
            double d1 = 3.0 * (y1 - y0);
            double d2 = 4.5 * (y2 - 2.0 * y1 + y0);
            double d3 = 4.5 * (y3 - 3.0 * y2 + 3.0 * y1 - y0);
            // Newton -> monomial:  p = m0 + m1 u + m2 u^2 + m3 u^3
            T.m[sr][0][j] = (float)d0;
            T.m[sr][1][j] = (float)(d1 - d2 / 3.0 + 2.0 * d3 / 9.0);
            T.m[sr][2][j] = (float)(d2 - d3);
            T.m[sr][3][j] = (float)d3;
        }
    }
    return T;
}

__constant__ Tab c_tab = make_tab();

// ---------------------------------------------------------------------------
// Per-element: result = c0[k] + u*(c1[k] + u*(c2[k] + u*c3[k]))
// where the affine part  id_gain*x + bias  is folded into c0,c1 per piece.
//   uf = (a*x+b)*6.5 + 7.5  ;  k0 = sat_trunc(uf) clamped to 13 ; u = uf-k0
//   k  = 14 iff uf > 14 (strict: uf==14 i.e. t==1 stays in piece 12)
// ---------------------------------------------------------------------------
__device__ __forceinline__ float eval_one(float x, float av, float bv,
                                          const float* tab) {
    float t  = fmaf(x, av, bv);
    float uf = fmaf(t, 6.5f, 7.5f);
    unsigned ku = __float2uint_rz(uf);         // negative -> 0 (saturating)
    int k0 = min((int)ku, 13);
    float u = uf - (float)k0;
    int k = (uf > 14.0f) ? 14 : k0;
    float c0 = tab[k];
    float c1 = tab[16 + k];
    float c2 = tab[32 + k];
    float c3 = tab[48 + k];
    float p = fmaf(c3, u, c2);
    p = fmaf(p, u, c1);
    return fmaf(p, u, c0);
}

// ---------------------------------------------------------------------------
// grid = 2048 blocks (1 per (b,c) plane), block = 256, 4 float4 per thread.
// ---------------------------------------------------------------------------
__global__ void __launch_bounds__(256)
kan_spline_fused(const float4* __restrict__ x,
                 const float*  __restrict__ a,
                 const float*  __restrict__ b,
                 const float*  __restrict__ alpha,
                 const float*  __restrict__ gain,
                 const float*  __restrict__ bias,
                 float4* __restrict__ out) {
    // tab[m*16 + k]: each LDS.32 hits distinct banks for distinct k.
    __shared__ float tab[64];

    int bid = blockIdx.x;
    int c = bid & (Cn - 1);
    int tid = threadIdx.x;

    if (tid < 15) {
        float av = a[c];
        float bv = b[c];
        float gv = gain[c];
        float bi = bias[c];
        // affine fold: gv*x + bi = g1*u + g0  with u = uf - keff
        float g1 = gv / (6.5f * av);
        float keff = (float)min(tid, 13);
        float g0 = fmaf(g1, keff - 7.5f - 6.5f * bv, bi);

        float c0 = g0, c1 = g1, c2 = 0.0f, c3 = 0.0f;
        int sr = tid - 1;                        // -1..13 ; valid pieces 0..12
        if (sr >= 0 && sr <= 12) {
            float al0 = alpha[c * Kn + sr];
            float al1 = alpha[c * Kn + sr + 1];
            float al2 = alpha[c * Kn + sr + 2];
            float al3 = alpha[c * Kn + sr + 3];
            const float (*M)[4] = c_tab.m[sr];
            c0 += fmaf(M[0][0], al0, fmaf(M[0][1], al1, fmaf(M[0][2], al2, M[0][3] * al3)));
            c1 += fmaf(M[1][0], al0, fmaf(M[1][1], al1, fmaf(M[1][2], al2, M[1][3] * al3)));
            c2  = fmaf(M[2][0], al0, fmaf(M[2][1], al1, fmaf(M[2][2], al2, M[2][3] * al3)));
            c3  = fmaf(M[3][0], al0, fmaf(M[3][1], al1, fmaf(M[3][2], al2, M[3][3] * al3)));
        }
        tab[tid]      = c0;
        tab[16 + tid] = c1;
        tab[32 + tid] = c2;
        tab[48 + tid] = c3;
    }
    float av = __ldg(a + c);
    float bv = __ldg(b + c);
    __syncthreads();

    // 4 float4 per thread: block covers one 1024-float4 plane
    int base = bid * 1024 + tid;
    float4 x0 = __ldg(x + base);
    float4 x1 = __ldg(x + base + 256);
    float4 x2 = __ldg(x + base + 512);
    float4 x3 = __ldg(x + base + 768);

    float4 o0, o1, o2, o3;
    o0.x = eval_one(x0.x, av, bv, tab);
    o0.y = eval_one(x0.y, av, bv, tab);
    o0.z = eval_one(x0.z, av, bv, tab);
    o0.w = eval_one(x0.w, av, bv, tab);
    o1.x = eval_one(x1.x, av, bv, tab);
    o1.y = eval_one(x1.y, av, bv, tab);
    o1.z = eval_one(x1.z, av, bv, tab);
    o1.w = eval_one(x1.w, av, bv, tab);
    o2.x = eval_one(x2.x, av, bv, tab);
    o2.y = eval_one(x2.y, av, bv, tab);
    o2.z = eval_one(x2.z, av, bv, tab);
    o2.w = eval_one(x2.w, av, bv, tab);
    o3.x = eval_one(x3.x, av, bv, tab);
    o3.y = eval_one(x3.y, av, bv, tab);
    o3.z = eval_one(x3.z, av, bv, tab);
    o3.w = eval_one(x3.w, av, bv, tab);

    out[base]       = o0;
    out[base + 256] = o1;
    out[base + 512] = o2;
    out[base + 768] = o3;
}

// ---------------------------------------------------------------------------
// Launch: d_in order = x, a, b, alpha, id_gain, bias
// ---------------------------------------------------------------------------
extern "C" void kernel_launch(void* const* d_in, const int* in_sizes, int n_in,
                              void* d_out, int out_size) {
    const float* x      = (const float*)d_in[0];
    const float* a      = (const float*)d_in[1];
    const float* b      = (const float*)d_in[2];
    const float* alpha  = (const float*)d_in[3];
    const float* gain   = (const float*)d_in[4];
    const float* bias   = (const float*)d_in[5];
    float* out = (float*)d_out;

    const int blocks = Bn * Cn;                   // 2048 planes
    kan_spline_fused<<<blocks, 256>>>((const float4*)x, a, b, alpha, gain, bias,
                                      (float4*)out);
}